// round 14
// baseline (speedup 1.0000x reference)
#include <cuda_runtime.h>
#include <cuda_fp16.h>
#include <math.h>
#include <stdint.h>

// Model dims
#define BB   1024
#define TT   20
#define CC   512
#define HH   8
#define LL   8
#define DD   64
#define MTOK (BB * TT)   // 20480 tokens

// ---------------------------------------------------------------------------
// Scratch (device globals: no allocation allowed in kernel_launch)
// ---------------------------------------------------------------------------
__device__ float  g_h  [MTOK * CC];          // residual (fp32)
__device__ __half g_xn [MTOK * CC];          // LN output (fp16)
__device__ float  g_qkv[MTOK * 3 * CC];      // qkv (fp32, attn input)
__device__ __half g_y  [MTOK * CC];          // attn output (fp16)
__device__ __half g_mid[MTOK * 4 * CC];      // GELU output (fp16)

// fp16, TRANSPOSED weights [N][K] per layer: attn | proj | fc1 | fc2
#define WATTN_OFF 0
#define WATTN_SZ  (LL * CC * 3 * CC)
#define WPROJ_OFF (WATTN_OFF + WATTN_SZ)
#define WPROJ_SZ  (LL * CC * CC)
#define WFC1_OFF  (WPROJ_OFF + WPROJ_SZ)
#define WFC1_SZ   (LL * CC * 4 * CC)
#define WFC2_OFF  (WFC1_OFF + WFC1_SZ)
#define WFC2_SZ   (LL * 4 * CC * CC)
#define WTOTAL    (WFC2_OFF + WFC2_SZ)
__device__ __half g_wt[WTOTAL];

__device__ __forceinline__ void cpa16(unsigned dst, const void* src) {
    asm volatile("cp.async.cg.shared.global [%0], [%1], 16;\n" :: "r"(dst), "l"(src));
}
#define CPA_COMMIT() asm volatile("cp.async.commit_group;\n" ::: "memory")
#define CPA_WAIT0()  asm volatile("cp.async.wait_group 0;\n" ::: "memory")
#define CPA_WAIT1()  asm volatile("cp.async.wait_group 1;\n" ::: "memory")

__device__ __forceinline__ uint32_t sm_u32(const void* p) {
    uint32_t a;
    asm("{ .reg .u64 t; cvta.to.shared.u64 t, %1; cvt.u32.u64 %0, t; }" : "=r"(a) : "l"(p));
    return a;
}
__device__ __forceinline__ void ldm_x4(uint32_t& r0, uint32_t& r1, uint32_t& r2,
                                       uint32_t& r3, uint32_t addr) {
    asm volatile("ldmatrix.sync.aligned.m8n8.x4.shared.b16 {%0,%1,%2,%3}, [%4];"
                 : "=r"(r0), "=r"(r1), "=r"(r2), "=r"(r3) : "r"(addr));
}

// ---------------------------------------------------------------------------
// Weight transpose + fp16 convert: src [K,N] fp32 -> dst [N,K] fp16.
// z: 0-7 qkv, 8-15 proj, 16-23 fc1, 24-31 fc2.
// ---------------------------------------------------------------------------
__global__ void wtrans_kernel(const float* __restrict__ aw,
                              const float* __restrict__ pw,
                              const float* __restrict__ f1,
                              const float* __restrict__ f2,
                              __half* __restrict__ dst) {
    __shared__ float tile[32][33];
    int type = blockIdx.z >> 3, l = blockIdx.z & 7;
    const float* src; __half* out; int K, N;
    if (type == 0)      { K = CC;     N = 3 * CC; src = aw + (size_t)l * K * N; out = dst + WATTN_OFF + (size_t)l * K * N; }
    else if (type == 1) { K = CC;     N = CC;     src = pw + (size_t)l * K * N; out = dst + WPROJ_OFF + (size_t)l * K * N; }
    else if (type == 2) { K = CC;     N = 4 * CC; src = f1 + (size_t)l * K * N; out = dst + WFC1_OFF  + (size_t)l * K * N; }
    else                { K = 4 * CC; N = CC;     src = f2 + (size_t)l * K * N; out = dst + WFC2_OFF  + (size_t)l * K * N; }
    int bx = blockIdx.x, by = blockIdx.y;
    if (bx * 32 >= N || by * 32 >= K) return;
    int tx = threadIdx.x, ty = threadIdx.y;   // 32 x 8
#pragma unroll
    for (int j = 0; j < 32; j += 8) {
        int k = by * 32 + ty + j, n = bx * 32 + tx;
        tile[ty + j][tx] = src[(size_t)k * N + n];
    }
    __syncthreads();
#pragma unroll
    for (int j = 0; j < 32; j += 8) {
        int n = bx * 32 + ty + j, k = by * 32 + tx;
        out[(size_t)n * K + k] = __float2half(tile[tx][ty + j]);
    }
}

// ---------------------------------------------------------------------------
// Encoder: h = x @ enc_w + enc_b + wpe[t+1]  (fp32)
// ---------------------------------------------------------------------------
__global__ void encode_kernel(const float* __restrict__ x,
                              const float* __restrict__ enc_w,
                              const float* __restrict__ enc_b,
                              const float* __restrict__ wpe,
                              float* __restrict__ out) {
    int i = blockIdx.x * blockDim.x + threadIdx.x;
    if (i >= MTOK * CC) return;
    int m = i / CC, c = i % CC;
    int t = m % TT;
    float x0 = x[m * 2 + 0], x1 = x[m * 2 + 1];
    out[i] = x0 * enc_w[c] + x1 * enc_w[CC + c] + enc_b[c] + wpe[(t + 1) * CC + c];
}

// ---------------------------------------------------------------------------
// LayerNorm: fp32 in, fp16 out (GEMM A operand / predictor input).
// ---------------------------------------------------------------------------
__global__ void ln_kernel(const float* __restrict__ in,
                          const float* __restrict__ w,
                          const float* __restrict__ b,
                          __half* __restrict__ out) {
    int row = blockIdx.x;
    const float* p = in + (size_t)row * CC;
    float v[4];
    float s = 0.f, sq = 0.f;
#pragma unroll
    for (int i = 0; i < 4; i++) {
        v[i] = p[threadIdx.x + i * 128];
        s  += v[i];
        sq += v[i] * v[i];
    }
#pragma unroll
    for (int o = 16; o > 0; o >>= 1) {
        s  += __shfl_xor_sync(0xffffffff, s, o);
        sq += __shfl_xor_sync(0xffffffff, sq, o);
    }
    __shared__ float red[8];
    int warp = threadIdx.x >> 5;
    if ((threadIdx.x & 31) == 0) { red[warp] = s; red[4 + warp] = sq; }
    __syncthreads();
    s  = red[0] + red[1] + red[2] + red[3];
    sq = red[4] + red[5] + red[6] + red[7];
    float mu  = s / CC;
    float var = sq / CC - mu * mu;
    float inv = rsqrtf(var + 1e-5f);
    __half* q = out + (size_t)row * CC;
#pragma unroll
    for (int i = 0; i < 4; i++) {
        int c = threadIdx.x + i * 128;
        q[c] = __float2half((v[i] - mu) * inv * w[c] + b[c]);
    }
}

// ---------------------------------------------------------------------------
// fp16 tensor-core GEMM (mma.sync m16n8k16, fp32 accum).
// CTA tile 128x128, KT=64, 256 threads, 8 warps (2x4), 64x32 warp tiles.
// A [M,K] fp16 row-major; Wt [N,K] fp16 row-major (pre-transposed).
// 3-stage cp.async pipeline (loads run 2 tiles ahead, wait_group 1),
// ONE __syncthreads per k-tile (3 buffers make the tail barrier redundant:
// tile t+2's store targets buf((t+2)%3), whose readers finished before the
// top-of-iteration barrier). Last iteration must wait_group 0.
// Smem: 16KB per A/B stage, XOR-swizzled 128B rows (conflict-free both ways).
// EPI: 0 = +bias -> fp32 out; 1 = +bias,GELU -> fp16 out; 2 = +bias,+res -> fp32.
// ---------------------------------------------------------------------------
#define KTT 64
#define HG_STG 16384
#define HG_SMEM (6 * HG_STG + 64)   // 3 stages x (A+B) = 96KB

template <int EPI>
__global__ void __launch_bounds__(256, 2)
hgemm_kernel(const __half* __restrict__ A,
             const __half* __restrict__ Wt,
             const float* __restrict__ bias,
             const float* __restrict__ res,
             void* __restrict__ outv,
             int Ndim, int Kdim) {
    extern __shared__ __align__(128) unsigned char hsm[];
    const uint32_t base = sm_u32(hsm);
    const uint32_t aS[3] = { base,              base + HG_STG,     base + 2 * HG_STG };
    const uint32_t bS[3] = { base + 3 * HG_STG, base + 4 * HG_STG, base + 5 * HG_STG };

    const int bm = blockIdx.y * 128, bn = blockIdx.x * 128;
    const int tid  = threadIdx.x;
    const int lane = tid & 31;
    const int wid  = tid >> 5;
    const int warp_m = (wid >> 2) * 64;   // 0 or 64
    const int warp_n = (wid & 3) * 32;    // 0,32,64,96
    const int NT = Kdim / KTT;

    float acc[4][4][4];
#pragma unroll
    for (int mi = 0; mi < 4; mi++)
#pragma unroll
        for (int ni = 0; ni < 4; ni++)
#pragma unroll
            for (int r = 0; r < 4; r++) acc[mi][ni][r] = 0.f;

    // cp.async mapping: idx = tid + 256*i (i<4): r = idx>>3, c16 = idx&7
    const int ld_r = tid >> 3;          // rows 0..31, +32 per i
    const int ld_c = tid & 7;

    // ldmatrix per-lane constants
    const int slot = lane >> 3, lr = lane & 7;
    const int da = slot >> 1;                                   // A: chunk parity
    const uint32_t rowA_b = (uint32_t)(warp_m + ((slot & 1) << 3) + lr) * 128;
    const int db = slot & 1;                                    // B: chunk parity
    const uint32_t rowB_b = (uint32_t)(warp_n + ((slot >> 1) << 3) + lr) * 128;

    auto load_tile = [&](int t, int bsel) {
        int k0 = t * KTT;
#pragma unroll
        for (int i = 0; i < 4; i++) {
            int r = ld_r + 32 * i;
            uint32_t doff = (uint32_t)(r * 128 + ((ld_c ^ (r & 7)) * 16));
            cpa16(aS[bsel] + doff, A  + (size_t)(bm + r) * Kdim + k0 + ld_c * 8);
            cpa16(bS[bsel] + doff, Wt + (size_t)(bn + r) * Kdim + k0 + ld_c * 8);
        }
        CPA_COMMIT();
    };

    // prologue: two tiles in flight
    load_tile(0, 0);
    load_tile(1, 1);

    int bsel = 0;        // t % 3
    int nsel = 2;        // (t+2) % 3
    for (int t = 0; t < NT; t++) {
        if (t + 1 < NT) { CPA_WAIT1(); } else { CPA_WAIT0(); }
        __syncthreads();
        if (t + 2 < NT) load_tile(t + 2, nsel);

        const uint32_t aT = aS[bsel], bT = bS[bsel];
#pragma unroll
        for (int s = 0; s < 4; s++) {
            const uint32_t aswz = (uint32_t)(((2 * s + da) ^ lr) << 4);
            const uint32_t bswz = (uint32_t)(((2 * s + db) ^ lr) << 4);
            uint32_t a[4][4], bf[4][2];
#pragma unroll
            for (int mi = 0; mi < 4; mi++)
                ldm_x4(a[mi][0], a[mi][1], a[mi][2], a[mi][3],
                       aT + rowA_b + mi * 2048 + aswz);
#pragma unroll
            for (int pi = 0; pi < 2; pi++) {
                uint32_t t0, t1, t2, t3;
                ldm_x4(t0, t1, t2, t3, bT + rowB_b + pi * 2048 + bswz);
                bf[2 * pi][0] = t0; bf[2 * pi][1] = t1;
                bf[2 * pi + 1][0] = t2; bf[2 * pi + 1][1] = t3;
            }
#pragma unroll
            for (int mi = 0; mi < 4; mi++)
#pragma unroll
                for (int ni = 0; ni < 4; ni++) {
                    asm volatile(
                        "mma.sync.aligned.m16n8k16.row.col.f32.f16.f16.f32 "
                        "{%0,%1,%2,%3}, {%4,%5,%6,%7}, {%8,%9}, {%0,%1,%2,%3};"
                        : "+f"(acc[mi][ni][0]), "+f"(acc[mi][ni][1]),
                          "+f"(acc[mi][ni][2]), "+f"(acc[mi][ni][3])
                        : "r"(a[mi][0]), "r"(a[mi][1]), "r"(a[mi][2]), "r"(a[mi][3]),
                          "r"(bf[ni][0]), "r"(bf[ni][1]));
                }
        }
        bsel = (bsel == 2) ? 0 : bsel + 1;
        nsel = (nsel == 2) ? 0 : nsel + 1;
    }

    // ---- epilogue ----
    const int g = lane >> 2, tig = lane & 3;
#pragma unroll
    for (int mi = 0; mi < 4; mi++) {
#pragma unroll
        for (int hf = 0; hf < 2; hf++) {
            int row = bm + warp_m + 16 * mi + g + 8 * hf;
#pragma unroll
            for (int ni = 0; ni < 4; ni++) {
                int col = bn + warp_n + 8 * ni + 2 * tig;
#pragma unroll
                for (int c = 0; c < 2; c++) {
                    float v = acc[mi][ni][2 * hf + c] + bias[col + c];
                    size_t off = (size_t)row * Ndim + col + c;
                    if (EPI == 1) {
                        v = 0.5f * v * (1.0f + erff(v * 0.70710678118654752440f));
                        ((__half*)outv)[off] = __float2half(v);
                    } else if (EPI == 2) {
                        ((float*)outv)[off] = v + res[off];
                    } else {
                        ((float*)outv)[off] = v;
                    }
                }
            }
        }
    }
}

// ---------------------------------------------------------------------------
// Attention: one 128-thread block per (batch, head); padded rows.
// qkv fp32 in, y fp16 out (proj A operand).
// ---------------------------------------------------------------------------
__global__ void attn_kernel(const float* __restrict__ qkv, __half* __restrict__ y) {
    __shared__ float Q[TT][DD + 1], K[TT][DD + 1], V[TT][DD + 1], S[TT][TT + 1];
    int b = blockIdx.x / HH, h = blockIdx.x % HH;
    const float* base = qkv + (size_t)b * TT * 3 * CC + h * DD;

    for (int idx = threadIdx.x; idx < TT * DD; idx += blockDim.x) {
        int t = idx / DD, d = idx % DD;
        const float* p = base + (size_t)t * 3 * CC + d;
        Q[t][d] = p[0];
        K[t][d] = p[CC];
        V[t][d] = p[2 * CC];
    }
    __syncthreads();

    const float scale = 0.125f;
    for (int idx = threadIdx.x; idx < TT * TT; idx += blockDim.x) {
        int tq = idx / TT, tk = idx % TT;
        if (tk <= tq) {
            float s = 0.f;
#pragma unroll
            for (int d = 0; d < DD; d++) s += Q[tq][d] * K[tk][d];
            S[tq][tk] = s * scale;
        }
    }
    __syncthreads();

    if (threadIdx.x < TT) {
        int tq = threadIdx.x;
        float mx = -1e30f;
        for (int tk = 0; tk <= tq; tk++) mx = fmaxf(mx, S[tq][tk]);
        float sum = 0.f;
        for (int tk = 0; tk <= tq; tk++) {
            float e = expf(S[tq][tk] - mx);
            S[tq][tk] = e;
            sum += e;
        }
        float inv = 1.f / sum;
        for (int tk = 0; tk <= tq; tk++) S[tq][tk] *= inv;
    }
    __syncthreads();

    for (int idx = threadIdx.x; idx < TT * DD; idx += blockDim.x) {
        int t = idx / DD, d = idx % DD;
        float o = 0.f;
        for (int tk = 0; tk <= t; tk++) o += S[t][tk] * V[tk][d];
        y[((size_t)b * TT + t) * CC + h * DD + d] = __float2half(o);
    }
}

// ---------------------------------------------------------------------------
// Predictor: xn (fp16) . pred_w (fp32), V=2. One warp per token.
// ---------------------------------------------------------------------------
__global__ void pred_kernel(const __half* __restrict__ xn,
                            const float* __restrict__ pw,
                            const float* __restrict__ pb,
                            float* __restrict__ out) {
    int m = blockIdx.x * 4 + (threadIdx.x >> 5);
    int lane = threadIdx.x & 31;
    const __half* p = xn + (size_t)m * CC;
    float a0 = 0.f, a1 = 0.f;
    for (int c = lane; c < CC; c += 32) {
        float v = __half2float(p[c]);
        a0 += v * pw[c * 2 + 0];
        a1 += v * pw[c * 2 + 1];
    }
#pragma unroll
    for (int o = 16; o > 0; o >>= 1) {
        a0 += __shfl_xor_sync(0xffffffff, a0, o);
        a1 += __shfl_xor_sync(0xffffffff, a1, o);
    }
    if (lane == 0) {
        out[m * 2 + 0] = a0 + pb[0];
        out[m * 2 + 1] = a1 + pb[1];
    }
}

// ---------------------------------------------------------------------------
// Launch
// ---------------------------------------------------------------------------
extern "C" void kernel_launch(void* const* d_in, const int* in_sizes, int n_in,
                              void* d_out, int out_size) {
    const float* x      = (const float*)d_in[0];
    const float* enc_w  = (const float*)d_in[1];
    const float* enc_b  = (const float*)d_in[2];
    const float* wpe    = (const float*)d_in[3];
    const float* ln1_w  = (const float*)d_in[4];
    const float* ln1_b  = (const float*)d_in[5];
    const float* attn_w = (const float*)d_in[6];
    const float* attn_b = (const float*)d_in[7];
    const float* proj_w = (const float*)d_in[8];
    const float* proj_b = (const float*)d_in[9];
    const float* ln2_w  = (const float*)d_in[10];
    const float* ln2_b  = (const float*)d_in[11];
    const float* fc1_w  = (const float*)d_in[12];
    const float* fc1_b  = (const float*)d_in[13];
    const float* fc2_w  = (const float*)d_in[14];
    const float* fc2_b  = (const float*)d_in[15];
    const float* lnf_w  = (const float*)d_in[16];
    const float* lnf_b  = (const float*)d_in[17];
    const float* pred_w = (const float*)d_in[18];
    const float* pred_b = (const float*)d_in[19];

    float *h, *qkv;
    __half *xn, *y, *mid, *wt;
    cudaGetSymbolAddress((void**)&h,   g_h);
    cudaGetSymbolAddress((void**)&xn,  g_xn);
    cudaGetSymbolAddress((void**)&qkv, g_qkv);
    cudaGetSymbolAddress((void**)&y,   g_y);
    cudaGetSymbolAddress((void**)&mid, g_mid);
    cudaGetSymbolAddress((void**)&wt,  g_wt);

    cudaFuncSetAttribute(hgemm_kernel<0>, cudaFuncAttributeMaxDynamicSharedMemorySize, HG_SMEM);
    cudaFuncSetAttribute(hgemm_kernel<1>, cudaFuncAttributeMaxDynamicSharedMemorySize, HG_SMEM);
    cudaFuncSetAttribute(hgemm_kernel<2>, cudaFuncAttributeMaxDynamicSharedMemorySize, HG_SMEM);

    // launch 0: weight transpose + fp16 convert (all 32 matrices)
    wtrans_kernel<<<dim3(64, 64, 32), dim3(32, 8)>>>(attn_w, proj_w, fc1_w, fc2_w, wt);
    // launch 1
    encode_kernel<<<(MTOK * CC + 255) / 256, 256>>>(x, enc_w, enc_b, wpe, h);

    dim3 gQKV(3 * CC / 128, MTOK / 128);   // 12 x 160
    dim3 gC  (CC / 128,     MTOK / 128);   //  4 x 160
    dim3 gFC1(4 * CC / 128, MTOK / 128);   // 16 x 160

    for (int l = 0; l < LL; l++) {
        ln_kernel<<<MTOK, 128>>>(h, ln1_w + l * CC, ln1_b + l * CC, xn);
        hgemm_kernel<0><<<gQKV, 256, HG_SMEM>>>(xn, wt + WATTN_OFF + (size_t)l * CC * 3 * CC,
                                                attn_b + (size_t)l * 3 * CC, nullptr,
                                                (void*)qkv, 3 * CC, CC);
        attn_kernel<<<BB * HH, 128>>>(qkv, y);
        hgemm_kernel<2><<<gC, 256, HG_SMEM>>>(y, wt + WPROJ_OFF + (size_t)l * CC * CC,
                                              proj_b + (size_t)l * CC, h,
                                              (void*)h, CC, CC);
        ln_kernel<<<MTOK, 128>>>(h, ln2_w + l * CC, ln2_b + l * CC, xn);
        hgemm_kernel<1><<<gFC1, 256, HG_SMEM>>>(xn, wt + WFC1_OFF + (size_t)l * CC * 4 * CC,
                                                fc1_b + (size_t)l * 4 * CC, nullptr,
                                                (void*)mid, 4 * CC, CC);
        hgemm_kernel<2><<<gC, 256, HG_SMEM>>>(mid, wt + WFC2_OFF + (size_t)l * 4 * CC * CC,
                                              fc2_b + (size_t)l * CC, h,
                                              (void*)h, CC, 4 * CC);
    }

    ln_kernel<<<MTOK, 128>>>(h, lnf_w, lnf_b, xn);
    pred_kernel<<<MTOK / 4, 128>>>(xn, pred_w, pred_b, (float*)d_out);
}

// round 15
// speedup vs baseline: 1.1541x; 1.1541x over previous
#include <cuda_runtime.h>
#include <cuda_fp16.h>
#include <math.h>
#include <stdint.h>

// Model dims
#define BB   1024
#define TT   20
#define CC   512
#define HH   8
#define LL   8
#define DD   64
#define MTOK (BB * TT)   // 20480 tokens

// ---------------------------------------------------------------------------
// Scratch (device globals: no allocation allowed in kernel_launch)
// ---------------------------------------------------------------------------
__device__ float  g_h  [MTOK * CC];          // residual (fp32)
__device__ __half g_xn [MTOK * CC];          // LN output (fp16)
__device__ __half g_qkv[MTOK * 3 * CC];      // qkv (fp16 now)
__device__ __half g_y  [MTOK * CC];          // attn output (fp16)
__device__ __half g_mid[MTOK * 4 * CC];      // GELU output (fp16)

// fp16, TRANSPOSED weights [N][K] per layer: attn | proj | fc1 | fc2
#define WATTN_OFF 0
#define WATTN_SZ  (LL * CC * 3 * CC)
#define WPROJ_OFF (WATTN_OFF + WATTN_SZ)
#define WPROJ_SZ  (LL * CC * CC)
#define WFC1_OFF  (WPROJ_OFF + WPROJ_SZ)
#define WFC1_SZ   (LL * CC * 4 * CC)
#define WFC2_OFF  (WFC1_OFF + WFC1_SZ)
#define WFC2_SZ   (LL * 4 * CC * CC)
#define WTOTAL    (WFC2_OFF + WFC2_SZ)
__device__ __half g_wt[WTOTAL];

__device__ __forceinline__ void cpa16(unsigned dst, const void* src) {
    asm volatile("cp.async.cg.shared.global [%0], [%1], 16;\n" :: "r"(dst), "l"(src));
}
#define CPA_COMMIT() asm volatile("cp.async.commit_group;\n" ::: "memory")
#define CPA_WAIT0()  asm volatile("cp.async.wait_group 0;\n" ::: "memory")

__device__ __forceinline__ uint32_t sm_u32(const void* p) {
    uint32_t a;
    asm("{ .reg .u64 t; cvta.to.shared.u64 t, %1; cvt.u32.u64 %0, t; }" : "=r"(a) : "l"(p));
    return a;
}
__device__ __forceinline__ void ldm_x4(uint32_t& r0, uint32_t& r1, uint32_t& r2,
                                       uint32_t& r3, uint32_t addr) {
    asm volatile("ldmatrix.sync.aligned.m8n8.x4.shared.b16 {%0,%1,%2,%3}, [%4];"
                 : "=r"(r0), "=r"(r1), "=r"(r2), "=r"(r3) : "r"(addr));
}

// ---------------------------------------------------------------------------
// Weight transpose + fp16 convert: src [K,N] fp32 -> dst [N,K] fp16.
// ---------------------------------------------------------------------------
__global__ void wtrans_kernel(const float* __restrict__ aw,
                              const float* __restrict__ pw,
                              const float* __restrict__ f1,
                              const float* __restrict__ f2,
                              __half* __restrict__ dst) {
    __shared__ float tile[32][33];
    int type = blockIdx.z >> 3, l = blockIdx.z & 7;
    const float* src; __half* out; int K, N;
    if (type == 0)      { K = CC;     N = 3 * CC; src = aw + (size_t)l * K * N; out = dst + WATTN_OFF + (size_t)l * K * N; }
    else if (type == 1) { K = CC;     N = CC;     src = pw + (size_t)l * K * N; out = dst + WPROJ_OFF + (size_t)l * K * N; }
    else if (type == 2) { K = CC;     N = 4 * CC; src = f1 + (size_t)l * K * N; out = dst + WFC1_OFF  + (size_t)l * K * N; }
    else                { K = 4 * CC; N = CC;     src = f2 + (size_t)l * K * N; out = dst + WFC2_OFF  + (size_t)l * K * N; }
    int bx = blockIdx.x, by = blockIdx.y;
    if (bx * 32 >= N || by * 32 >= K) return;
    int tx = threadIdx.x, ty = threadIdx.y;   // 32 x 8
#pragma unroll
    for (int j = 0; j < 32; j += 8) {
        int k = by * 32 + ty + j, n = bx * 32 + tx;
        tile[ty + j][tx] = src[(size_t)k * N + n];
    }
    __syncthreads();
#pragma unroll
    for (int j = 0; j < 32; j += 8) {
        int n = bx * 32 + ty + j, k = by * 32 + tx;
        out[(size_t)n * K + k] = __float2half(tile[tx][ty + j]);
    }
}

// ---------------------------------------------------------------------------
// Encoder: h = x @ enc_w + enc_b + wpe[t+1]  (fp32)
// ---------------------------------------------------------------------------
__global__ void encode_kernel(const float* __restrict__ x,
                              const float* __restrict__ enc_w,
                              const float* __restrict__ enc_b,
                              const float* __restrict__ wpe,
                              float* __restrict__ out) {
    int i = blockIdx.x * blockDim.x + threadIdx.x;
    if (i >= MTOK * CC) return;
    int m = i / CC, c = i % CC;
    int t = m % TT;
    float x0 = x[m * 2 + 0], x1 = x[m * 2 + 1];
    out[i] = x0 * enc_w[c] + x1 * enc_w[CC + c] + enc_b[c] + wpe[(t + 1) * CC + c];
}

// ---------------------------------------------------------------------------
// LayerNorm: fp32 in (float4), fp16 out (half2). One 128-thread block per row.
// ---------------------------------------------------------------------------
__global__ void ln_kernel(const float* __restrict__ in,
                          const float* __restrict__ w,
                          const float* __restrict__ b,
                          __half* __restrict__ out) {
    int row = blockIdx.x;
    const float4* p4 = (const float4*)(in + (size_t)row * CC);
    float4 v = p4[threadIdx.x];
    float s  = v.x + v.y + v.z + v.w;
    float sq = v.x * v.x + v.y * v.y + v.z * v.z + v.w * v.w;
#pragma unroll
    for (int o = 16; o > 0; o >>= 1) {
        s  += __shfl_xor_sync(0xffffffff, s, o);
        sq += __shfl_xor_sync(0xffffffff, sq, o);
    }
    __shared__ float red[8];
    int warp = threadIdx.x >> 5;
    if ((threadIdx.x & 31) == 0) { red[warp] = s; red[4 + warp] = sq; }
    __syncthreads();
    s  = red[0] + red[1] + red[2] + red[3];
    sq = red[4] + red[5] + red[6] + red[7];
    float mu  = s / CC;
    float var = sq / CC - mu * mu;
    float inv = rsqrtf(var + 1e-5f);
    float4 wv = ((const float4*)w)[threadIdx.x];
    float4 bv = ((const float4*)b)[threadIdx.x];
    float r0 = (v.x - mu) * inv * wv.x + bv.x;
    float r1 = (v.y - mu) * inv * wv.y + bv.y;
    float r2 = (v.z - mu) * inv * wv.z + bv.z;
    float r3 = (v.w - mu) * inv * wv.w + bv.w;
    __half2* q2 = (__half2*)(out + (size_t)row * CC);
    q2[threadIdx.x * 2 + 0] = __floats2half2_rn(r0, r1);
    q2[threadIdx.x * 2 + 1] = __floats2half2_rn(r2, r3);
}

// ---------------------------------------------------------------------------
// fp16 tensor-core GEMM (mma.sync m16n8k16, fp32 accum) — R12 2-stage loop.
// CTA tile 128x128, KT=64, 256 threads, 8 warps (2x4), 64x32 warp tiles.
// A [M,K] fp16 row-major; Wt [N,K] fp16 row-major (pre-transposed).
// Smem 16B chunks XOR-swizzled; double-buffered (4 x 16KB).
// EPI: 0 = +bias -> fp16 out (qkv); 1 = +bias,GELU -> fp16; 2 = +bias,+res -> fp32.
// ---------------------------------------------------------------------------
#define KTT 64
#define HG_SMEM (4 * 16384 + 64)

template <int EPI>
__global__ void __launch_bounds__(256, 2)
hgemm_kernel(const __half* __restrict__ A,
             const __half* __restrict__ Wt,
             const float* __restrict__ bias,
             const float* __restrict__ res,
             void* __restrict__ outv,
             int Ndim, int Kdim) {
    extern __shared__ __align__(128) unsigned char hsm[];
    const uint32_t base = sm_u32(hsm);
    const uint32_t aS[2] = { base,         base + 16384 };
    const uint32_t bS[2] = { base + 32768, base + 49152 };

    const int bm = blockIdx.y * 128, bn = blockIdx.x * 128;
    const int tid  = threadIdx.x;
    const int lane = tid & 31;
    const int wid  = tid >> 5;
    const int warp_m = (wid >> 2) * 64;   // 0 or 64
    const int warp_n = (wid & 3) * 32;    // 0,32,64,96
    const int NT = Kdim / KTT;

    float acc[4][4][4];
#pragma unroll
    for (int mi = 0; mi < 4; mi++)
#pragma unroll
        for (int ni = 0; ni < 4; ni++)
#pragma unroll
            for (int r = 0; r < 4; r++) acc[mi][ni][r] = 0.f;

    const int ld_r = tid >> 3;
    const int ld_c = tid & 7;

    const int slot = lane >> 3, lr = lane & 7;
    const int da = slot >> 1;
    const uint32_t rowA_b = (uint32_t)(warp_m + ((slot & 1) << 3) + lr) * 128;
    const int db = slot & 1;
    const uint32_t rowB_b = (uint32_t)(warp_n + ((slot >> 1) << 3) + lr) * 128;

    auto load_tile = [&](int t, int bsel) {
        int k0 = t * KTT;
#pragma unroll
        for (int i = 0; i < 4; i++) {
            int r = ld_r + 32 * i;
            uint32_t doff = (uint32_t)(r * 128 + ((ld_c ^ (r & 7)) * 16));
            cpa16(aS[bsel] + doff, A  + (size_t)(bm + r) * Kdim + k0 + ld_c * 8);
            cpa16(bS[bsel] + doff, Wt + (size_t)(bn + r) * Kdim + k0 + ld_c * 8);
        }
        CPA_COMMIT();
    };

    load_tile(0, 0);

    for (int t = 0; t < NT; t++) {
        CPA_WAIT0();
        __syncthreads();
        if (t + 1 < NT) load_tile(t + 1, (t + 1) & 1);

        const uint32_t aT = aS[t & 1], bT = bS[t & 1];
#pragma unroll
        for (int s = 0; s < 4; s++) {
            const uint32_t aswz = (uint32_t)(((2 * s + da) ^ lr) << 4);
            const uint32_t bswz = (uint32_t)(((2 * s + db) ^ lr) << 4);
            uint32_t a[4][4], bf[4][2];
#pragma unroll
            for (int mi = 0; mi < 4; mi++)
                ldm_x4(a[mi][0], a[mi][1], a[mi][2], a[mi][3],
                       aT + rowA_b + mi * 2048 + aswz);
#pragma unroll
            for (int pi = 0; pi < 2; pi++) {
                uint32_t t0, t1, t2, t3;
                ldm_x4(t0, t1, t2, t3, bT + rowB_b + pi * 2048 + bswz);
                bf[2 * pi][0] = t0; bf[2 * pi][1] = t1;
                bf[2 * pi + 1][0] = t2; bf[2 * pi + 1][1] = t3;
            }
#pragma unroll
            for (int mi = 0; mi < 4; mi++)
#pragma unroll
                for (int ni = 0; ni < 4; ni++) {
                    asm volatile(
                        "mma.sync.aligned.m16n8k16.row.col.f32.f16.f16.f32 "
                        "{%0,%1,%2,%3}, {%4,%5,%6,%7}, {%8,%9}, {%0,%1,%2,%3};"
                        : "+f"(acc[mi][ni][0]), "+f"(acc[mi][ni][1]),
                          "+f"(acc[mi][ni][2]), "+f"(acc[mi][ni][3])
                        : "r"(a[mi][0]), "r"(a[mi][1]), "r"(a[mi][2]), "r"(a[mi][3]),
                          "r"(bf[ni][0]), "r"(bf[ni][1]));
                }
        }
        __syncthreads();
    }

    // ---- epilogue ----
    const int g = lane >> 2, tig = lane & 3;
#pragma unroll
    for (int mi = 0; mi < 4; mi++) {
#pragma unroll
        for (int hf = 0; hf < 2; hf++) {
            int row = bm + warp_m + 16 * mi + g + 8 * hf;
#pragma unroll
            for (int ni = 0; ni < 4; ni++) {
                int col = bn + warp_n + 8 * ni + 2 * tig;
                size_t off = (size_t)row * Ndim + col;
                float v0 = acc[mi][ni][2 * hf + 0] + bias[col + 0];
                float v1 = acc[mi][ni][2 * hf + 1] + bias[col + 1];
                if (EPI == 0) {
                    *(__half2*)((__half*)outv + off) = __floats2half2_rn(v0, v1);
                } else if (EPI == 1) {
                    v0 = 0.5f * v0 * (1.0f + erff(v0 * 0.70710678118654752440f));
                    v1 = 0.5f * v1 * (1.0f + erff(v1 * 0.70710678118654752440f));
                    *(__half2*)((__half*)outv + off) = __floats2half2_rn(v0, v1);
                } else {
                    ((float*)outv)[off + 0] = v0 + res[off + 0];
                    ((float*)outv)[off + 1] = v1 + res[off + 1];
                }
            }
        }
    }
}

// ---------------------------------------------------------------------------
// Attention: one 128-thread block per (batch, head); padded rows.
// qkv fp16 in (half2 loads), y fp16 out.
// ---------------------------------------------------------------------------
__global__ void attn_kernel(const __half* __restrict__ qkv, __half* __restrict__ y) {
    __shared__ float Q[TT][DD + 1], K[TT][DD + 1], V[TT][DD + 1], S[TT][TT + 1];
    int b = blockIdx.x / HH, h = blockIdx.x % HH;
    const __half* base = qkv + (size_t)b * TT * 3 * CC + h * DD;

    for (int idx = threadIdx.x; idx < TT * (DD / 2); idx += blockDim.x) {
        int t = idx / (DD / 2), d2 = idx % (DD / 2);
        const __half* p = base + (size_t)t * 3 * CC + 2 * d2;
        float2 q2 = __half22float2(*(const __half2*)(p));
        float2 k2 = __half22float2(*(const __half2*)(p + CC));
        float2 v2 = __half22float2(*(const __half2*)(p + 2 * CC));
        Q[t][2 * d2] = q2.x; Q[t][2 * d2 + 1] = q2.y;
        K[t][2 * d2] = k2.x; K[t][2 * d2 + 1] = k2.y;
        V[t][2 * d2] = v2.x; V[t][2 * d2 + 1] = v2.y;
    }
    __syncthreads();

    const float scale = 0.125f;
    for (int idx = threadIdx.x; idx < TT * TT; idx += blockDim.x) {
        int tq = idx / TT, tk = idx % TT;
        if (tk <= tq) {
            float s = 0.f;
#pragma unroll
            for (int d = 0; d < DD; d++) s += Q[tq][d] * K[tk][d];
            S[tq][tk] = s * scale;
        }
    }
    __syncthreads();

    if (threadIdx.x < TT) {
        int tq = threadIdx.x;
        float mx = -1e30f;
        for (int tk = 0; tk <= tq; tk++) mx = fmaxf(mx, S[tq][tk]);
        float sum = 0.f;
        for (int tk = 0; tk <= tq; tk++) {
            float e = expf(S[tq][tk] - mx);
            S[tq][tk] = e;
            sum += e;
        }
        float inv = 1.f / sum;
        for (int tk = 0; tk <= tq; tk++) S[tq][tk] *= inv;
    }
    __syncthreads();

    for (int idx = threadIdx.x; idx < TT * DD; idx += blockDim.x) {
        int t = idx / DD, d = idx % DD;
        float o = 0.f;
        for (int tk = 0; tk <= t; tk++) o += S[t][tk] * V[tk][d];
        y[((size_t)b * TT + t) * CC + h * DD + d] = __float2half(o);
    }
}

// ---------------------------------------------------------------------------
// Predictor: xn (fp16) . pred_w (fp32), V=2. One warp per token.
// ---------------------------------------------------------------------------
__global__ void pred_kernel(const __half* __restrict__ xn,
                            const float* __restrict__ pw,
                            const float* __restrict__ pb,
                            float* __restrict__ out) {
    int m = blockIdx.x * 4 + (threadIdx.x >> 5);
    int lane = threadIdx.x & 31;
    const __half* p = xn + (size_t)m * CC;
    float a0 = 0.f, a1 = 0.f;
    for (int c = lane; c < CC; c += 32) {
        float v = __half2float(p[c]);
        a0 += v * pw[c * 2 + 0];
        a1 += v * pw[c * 2 + 1];
    }
#pragma unroll
    for (int o = 16; o > 0; o >>= 1) {
        a0 += __shfl_xor_sync(0xffffffff, a0, o);
        a1 += __shfl_xor_sync(0xffffffff, a1, o);
    }
    if (lane == 0) {
        out[m * 2 + 0] = a0 + pb[0];
        out[m * 2 + 1] = a1 + pb[1];
    }
}

// ---------------------------------------------------------------------------
// Launch
// ---------------------------------------------------------------------------
extern "C" void kernel_launch(void* const* d_in, const int* in_sizes, int n_in,
                              void* d_out, int out_size) {
    const float* x      = (const float*)d_in[0];
    const float* enc_w  = (const float*)d_in[1];
    const float* enc_b  = (const float*)d_in[2];
    const float* wpe    = (const float*)d_in[3];
    const float* ln1_w  = (const float*)d_in[4];
    const float* ln1_b  = (const float*)d_in[5];
    const float* attn_w = (const float*)d_in[6];
    const float* attn_b = (const float*)d_in[7];
    const float* proj_w = (const float*)d_in[8];
    const float* proj_b = (const float*)d_in[9];
    const float* ln2_w  = (const float*)d_in[10];
    const float* ln2_b  = (const float*)d_in[11];
    const float* fc1_w  = (const float*)d_in[12];
    const float* fc1_b  = (const float*)d_in[13];
    const float* fc2_w  = (const float*)d_in[14];
    const float* fc2_b  = (const float*)d_in[15];
    const float* lnf_w  = (const float*)d_in[16];
    const float* lnf_b  = (const float*)d_in[17];
    const float* pred_w = (const float*)d_in[18];
    const float* pred_b = (const float*)d_in[19];

    float* h;
    __half *xn, *qkv, *y, *mid, *wt;
    cudaGetSymbolAddress((void**)&h,   g_h);
    cudaGetSymbolAddress((void**)&xn,  g_xn);
    cudaGetSymbolAddress((void**)&qkv, g_qkv);
    cudaGetSymbolAddress((void**)&y,   g_y);
    cudaGetSymbolAddress((void**)&mid, g_mid);
    cudaGetSymbolAddress((void**)&wt,  g_wt);

    cudaFuncSetAttribute(hgemm_kernel<0>, cudaFuncAttributeMaxDynamicSharedMemorySize, HG_SMEM);
    cudaFuncSetAttribute(hgemm_kernel<1>, cudaFuncAttributeMaxDynamicSharedMemorySize, HG_SMEM);
    cudaFuncSetAttribute(hgemm_kernel<2>, cudaFuncAttributeMaxDynamicSharedMemorySize, HG_SMEM);

    // launch 0: weight transpose + fp16 convert
    wtrans_kernel<<<dim3(64, 64, 32), dim3(32, 8)>>>(attn_w, proj_w, fc1_w, fc2_w, wt);
    // launch 1
    encode_kernel<<<(MTOK * CC + 255) / 256, 256>>>(x, enc_w, enc_b, wpe, h);

    dim3 gQKV(3 * CC / 128, MTOK / 128);   // 12 x 160
    dim3 gC  (CC / 128,     MTOK / 128);   //  4 x 160
    dim3 gFC1(4 * CC / 128, MTOK / 128);   // 16 x 160

    for (int l = 0; l < LL; l++) {
        ln_kernel<<<MTOK, 128>>>(h, ln1_w + l * CC, ln1_b + l * CC, xn);
        hgemm_kernel<0><<<gQKV, 256, HG_SMEM>>>(xn, wt + WATTN_OFF + (size_t)l * CC * 3 * CC,
                                                attn_b + (size_t)l * 3 * CC, nullptr,
                                                (void*)qkv, 3 * CC, CC);
        attn_kernel<<<BB * HH, 128>>>(qkv, y);
        hgemm_kernel<2><<<gC, 256, HG_SMEM>>>(y, wt + WPROJ_OFF + (size_t)l * CC * CC,
                                              proj_b + (size_t)l * CC, h,
                                              (void*)h, CC, CC);
        ln_kernel<<<MTOK, 128>>>(h, ln2_w + l * CC, ln2_b + l * CC, xn);
        hgemm_kernel<1><<<gFC1, 256, HG_SMEM>>>(xn, wt + WFC1_OFF + (size_t)l * CC * 4 * CC,
                                                fc1_b + (size_t)l * 4 * CC, nullptr,
                                                (void*)mid, 4 * CC, CC);
        hgemm_kernel<2><<<gC, 256, HG_SMEM>>>(mid, wt + WFC2_OFF + (size_t)l * 4 * CC * CC,
                                              fc2_b + (size_t)l * CC, h,
                                              (void*)h, CC, 4 * CC);
    }

    ln_kernel<<<MTOK, 128>>>(h, lnf_w, lnf_b, xn);
    pred_kernel<<<MTOK / 4, 128>>>(xn, pred_w, pred_b, (float*)d_out);
}

// round 16
// speedup vs baseline: 1.1590x; 1.0042x over previous
#include <cuda_runtime.h>
#include <cuda_fp16.h>
#include <math.h>
#include <stdint.h>

// Model dims
#define BB   1024
#define TT   20
#define CC   512
#define HH   8
#define LL   8
#define DD   64
#define MTOK (BB * TT)   // 20480 tokens

// ---------------------------------------------------------------------------
// Scratch (device globals: no allocation allowed in kernel_launch)
// ---------------------------------------------------------------------------
__device__ float  g_h  [MTOK * CC];          // residual (fp32)
__device__ __half g_xn [MTOK * CC];          // LN output (fp16)
__device__ __half g_qkv[MTOK * 3 * CC];      // qkv (fp16)
__device__ __half g_y  [MTOK * CC];          // attn output (fp16)
__device__ __half g_mid[MTOK * 4 * CC];      // GELU output (fp16)

// fp16, TRANSPOSED weights [N][K] per layer: attn | proj | fc1 | fc2
#define WATTN_OFF 0
#define WATTN_SZ  (LL * CC * 3 * CC)
#define WPROJ_OFF (WATTN_OFF + WATTN_SZ)
#define WPROJ_SZ  (LL * CC * CC)
#define WFC1_OFF  (WPROJ_OFF + WPROJ_SZ)
#define WFC1_SZ   (LL * CC * 4 * CC)
#define WFC2_OFF  (WFC1_OFF + WFC1_SZ)
#define WFC2_SZ   (LL * 4 * CC * CC)
#define WTOTAL    (WFC2_OFF + WFC2_SZ)
__device__ __half g_wt[WTOTAL];

__device__ __forceinline__ void cpa16(unsigned dst, const void* src) {
    asm volatile("cp.async.cg.shared.global [%0], [%1], 16;\n" :: "r"(dst), "l"(src));
}
#define CPA_COMMIT() asm volatile("cp.async.commit_group;\n" ::: "memory")
#define CPA_WAIT0()  asm volatile("cp.async.wait_group 0;\n" ::: "memory")

__device__ __forceinline__ uint32_t sm_u32(const void* p) {
    uint32_t a;
    asm("{ .reg .u64 t; cvta.to.shared.u64 t, %1; cvt.u32.u64 %0, t; }" : "=r"(a) : "l"(p));
    return a;
}
__device__ __forceinline__ void ldm_x4(uint32_t& r0, uint32_t& r1, uint32_t& r2,
                                       uint32_t& r3, uint32_t addr) {
    asm volatile("ldmatrix.sync.aligned.m8n8.x4.shared.b16 {%0,%1,%2,%3}, [%4];"
                 : "=r"(r0), "=r"(r1), "=r"(r2), "=r"(r3) : "r"(addr));
}

// ---------------------------------------------------------------------------
// Weight transpose + fp16 convert: src [K,N] fp32 -> dst [N,K] fp16.
// ---------------------------------------------------------------------------
__global__ void wtrans_kernel(const float* __restrict__ aw,
                              const float* __restrict__ pw,
                              const float* __restrict__ f1,
                              const float* __restrict__ f2,
                              __half* __restrict__ dst) {
    __shared__ float tile[32][33];
    int type = blockIdx.z >> 3, l = blockIdx.z & 7;
    const float* src; __half* out; int K, N;
    if (type == 0)      { K = CC;     N = 3 * CC; src = aw + (size_t)l * K * N; out = dst + WATTN_OFF + (size_t)l * K * N; }
    else if (type == 1) { K = CC;     N = CC;     src = pw + (size_t)l * K * N; out = dst + WPROJ_OFF + (size_t)l * K * N; }
    else if (type == 2) { K = CC;     N = 4 * CC; src = f1 + (size_t)l * K * N; out = dst + WFC1_OFF  + (size_t)l * K * N; }
    else                { K = 4 * CC; N = CC;     src = f2 + (size_t)l * K * N; out = dst + WFC2_OFF  + (size_t)l * K * N; }
    int bx = blockIdx.x, by = blockIdx.y;
    if (bx * 32 >= N || by * 32 >= K) return;
    int tx = threadIdx.x, ty = threadIdx.y;   // 32 x 8
#pragma unroll
    for (int j = 0; j < 32; j += 8) {
        int k = by * 32 + ty + j, n = bx * 32 + tx;
        tile[ty + j][tx] = src[(size_t)k * N + n];
    }
    __syncthreads();
#pragma unroll
    for (int j = 0; j < 32; j += 8) {
        int n = bx * 32 + ty + j, k = by * 32 + tx;
        out[(size_t)n * K + k] = __float2half(tile[tx][ty + j]);
    }
}

// ---------------------------------------------------------------------------
// Encoder: h = x @ enc_w + enc_b + wpe[t+1]  (fp32)
// ---------------------------------------------------------------------------
__global__ void encode_kernel(const float* __restrict__ x,
                              const float* __restrict__ enc_w,
                              const float* __restrict__ enc_b,
                              const float* __restrict__ wpe,
                              float* __restrict__ out) {
    int i = blockIdx.x * blockDim.x + threadIdx.x;
    if (i >= MTOK * CC) return;
    int m = i / CC, c = i % CC;
    int t = m % TT;
    float x0 = x[m * 2 + 0], x1 = x[m * 2 + 1];
    out[i] = x0 * enc_w[c] + x1 * enc_w[CC + c] + enc_b[c] + wpe[(t + 1) * CC + c];
}

// ---------------------------------------------------------------------------
// LayerNorm: fp32 in (float4), fp16 out (half2). One 128-thread block per row.
// ---------------------------------------------------------------------------
__global__ void ln_kernel(const float* __restrict__ in,
                          const float* __restrict__ w,
                          const float* __restrict__ b,
                          __half* __restrict__ out) {
    int row = blockIdx.x;
    const float4* p4 = (const float4*)(in + (size_t)row * CC);
    float4 v = p4[threadIdx.x];
    float s  = v.x + v.y + v.z + v.w;
    float sq = v.x * v.x + v.y * v.y + v.z * v.z + v.w * v.w;
#pragma unroll
    for (int o = 16; o > 0; o >>= 1) {
        s  += __shfl_xor_sync(0xffffffff, s, o);
        sq += __shfl_xor_sync(0xffffffff, sq, o);
    }
    __shared__ float red[8];
    int warp = threadIdx.x >> 5;
    if ((threadIdx.x & 31) == 0) { red[warp] = s; red[4 + warp] = sq; }
    __syncthreads();
    s  = red[0] + red[1] + red[2] + red[3];
    sq = red[4] + red[5] + red[6] + red[7];
    float mu  = s / CC;
    float var = sq / CC - mu * mu;
    float inv = rsqrtf(var + 1e-5f);
    float4 wv = ((const float4*)w)[threadIdx.x];
    float4 bv = ((const float4*)b)[threadIdx.x];
    float r0 = (v.x - mu) * inv * wv.x + bv.x;
    float r1 = (v.y - mu) * inv * wv.y + bv.y;
    float r2 = (v.z - mu) * inv * wv.z + bv.z;
    float r3 = (v.w - mu) * inv * wv.w + bv.w;
    __half2* q2 = (__half2*)(out + (size_t)row * CC);
    q2[threadIdx.x * 2 + 0] = __floats2half2_rn(r0, r1);
    q2[threadIdx.x * 2 + 1] = __floats2half2_rn(r2, r3);
}

// ---------------------------------------------------------------------------
// fp16 tensor-core GEMM (mma.sync m16n8k16, fp32 accum) — banked R15 loop.
// ---------------------------------------------------------------------------
#define KTT 64
#define HG_SMEM (4 * 16384 + 64)

template <int EPI>
__global__ void __launch_bounds__(256, 2)
hgemm_kernel(const __half* __restrict__ A,
             const __half* __restrict__ Wt,
             const float* __restrict__ bias,
             const float* __restrict__ res,
             void* __restrict__ outv,
             int Ndim, int Kdim) {
    extern __shared__ __align__(128) unsigned char hsm[];
    const uint32_t base = sm_u32(hsm);
    const uint32_t aS[2] = { base,         base + 16384 };
    const uint32_t bS[2] = { base + 32768, base + 49152 };

    const int bm = blockIdx.y * 128, bn = blockIdx.x * 128;
    const int tid  = threadIdx.x;
    const int lane = tid & 31;
    const int wid  = tid >> 5;
    const int warp_m = (wid >> 2) * 64;
    const int warp_n = (wid & 3) * 32;
    const int NT = Kdim / KTT;

    float acc[4][4][4];
#pragma unroll
    for (int mi = 0; mi < 4; mi++)
#pragma unroll
        for (int ni = 0; ni < 4; ni++)
#pragma unroll
            for (int r = 0; r < 4; r++) acc[mi][ni][r] = 0.f;

    const int ld_r = tid >> 3;
    const int ld_c = tid & 7;

    const int slot = lane >> 3, lr = lane & 7;
    const int da = slot >> 1;
    const uint32_t rowA_b = (uint32_t)(warp_m + ((slot & 1) << 3) + lr) * 128;
    const int db = slot & 1;
    const uint32_t rowB_b = (uint32_t)(warp_n + ((slot >> 1) << 3) + lr) * 128;

    auto load_tile = [&](int t, int bsel) {
        int k0 = t * KTT;
#pragma unroll
        for (int i = 0; i < 4; i++) {
            int r = ld_r + 32 * i;
            uint32_t doff = (uint32_t)(r * 128 + ((ld_c ^ (r & 7)) * 16));
            cpa16(aS[bsel] + doff, A  + (size_t)(bm + r) * Kdim + k0 + ld_c * 8);
            cpa16(bS[bsel] + doff, Wt + (size_t)(bn + r) * Kdim + k0 + ld_c * 8);
        }
        CPA_COMMIT();
    };

    load_tile(0, 0);

    for (int t = 0; t < NT; t++) {
        CPA_WAIT0();
        __syncthreads();
        if (t + 1 < NT) load_tile(t + 1, (t + 1) & 1);

        const uint32_t aT = aS[t & 1], bT = bS[t & 1];
#pragma unroll
        for (int s = 0; s < 4; s++) {
            const uint32_t aswz = (uint32_t)(((2 * s + da) ^ lr) << 4);
            const uint32_t bswz = (uint32_t)(((2 * s + db) ^ lr) << 4);
            uint32_t a[4][4], bf[4][2];
#pragma unroll
            for (int mi = 0; mi < 4; mi++)
                ldm_x4(a[mi][0], a[mi][1], a[mi][2], a[mi][3],
                       aT + rowA_b + mi * 2048 + aswz);
#pragma unroll
            for (int pi = 0; pi < 2; pi++) {
                uint32_t t0, t1, t2, t3;
                ldm_x4(t0, t1, t2, t3, bT + rowB_b + pi * 2048 + bswz);
                bf[2 * pi][0] = t0; bf[2 * pi][1] = t1;
                bf[2 * pi + 1][0] = t2; bf[2 * pi + 1][1] = t3;
            }
#pragma unroll
            for (int mi = 0; mi < 4; mi++)
#pragma unroll
                for (int ni = 0; ni < 4; ni++) {
                    asm volatile(
                        "mma.sync.aligned.m16n8k16.row.col.f32.f16.f16.f32 "
                        "{%0,%1,%2,%3}, {%4,%5,%6,%7}, {%8,%9}, {%0,%1,%2,%3};"
                        : "+f"(acc[mi][ni][0]), "+f"(acc[mi][ni][1]),
                          "+f"(acc[mi][ni][2]), "+f"(acc[mi][ni][3])
                        : "r"(a[mi][0]), "r"(a[mi][1]), "r"(a[mi][2]), "r"(a[mi][3]),
                          "r"(bf[ni][0]), "r"(bf[ni][1]));
                }
        }
        __syncthreads();
    }

    // ---- epilogue ----
    const int g = lane >> 2, tig = lane & 3;
#pragma unroll
    for (int mi = 0; mi < 4; mi++) {
#pragma unroll
        for (int hf = 0; hf < 2; hf++) {
            int row = bm + warp_m + 16 * mi + g + 8 * hf;
#pragma unroll
            for (int ni = 0; ni < 4; ni++) {
                int col = bn + warp_n + 8 * ni + 2 * tig;
                size_t off = (size_t)row * Ndim + col;
                float v0 = acc[mi][ni][2 * hf + 0] + bias[col + 0];
                float v1 = acc[mi][ni][2 * hf + 1] + bias[col + 1];
                if (EPI == 0) {
                    *(__half2*)((__half*)outv + off) = __floats2half2_rn(v0, v1);
                } else if (EPI == 1) {
                    v0 = 0.5f * v0 * (1.0f + erff(v0 * 0.70710678118654752440f));
                    v1 = 0.5f * v1 * (1.0f + erff(v1 * 0.70710678118654752440f));
                    *(__half2*)((__half*)outv + off) = __floats2half2_rn(v0, v1);
                } else {
                    ((float*)outv)[off + 0] = v0 + res[off + 0];
                    ((float*)outv)[off + 1] = v1 + res[off + 1];
                }
            }
        }
    }
}

// ---------------------------------------------------------------------------
// Attention: 2 heads per 256-thread block (grid BB*4). Padded smem rows.
// qkv fp16 in (half2 loads, 256B-coalesced per head-pair), y fp16 out.
// ---------------------------------------------------------------------------
__global__ void attn_kernel(const __half* __restrict__ qkv, __half* __restrict__ y) {
    __shared__ float Q[2][TT][DD + 1], K[2][TT][DD + 1], V[2][TT][DD + 1];
    __shared__ float S[2][TT][TT + 1];
    int b  = blockIdx.x >> 2;
    int hp = blockIdx.x & 3;             // head pair: heads 2*hp, 2*hp+1
    const __half* base = qkv + (size_t)b * TT * 3 * CC + hp * 2 * DD;

    // load: per t, 64 half2 covering both heads (128 halves) per stream
    for (int idx = threadIdx.x; idx < TT * 64; idx += 256) {
        int t = idx >> 6, c2 = idx & 63;
        int e = c2 >> 5, d = (c2 & 31) * 2;
        const __half* rowp = base + (size_t)t * 3 * CC + c2 * 2;
        float2 q2 = __half22float2(*(const __half2*)(rowp));
        float2 k2 = __half22float2(*(const __half2*)(rowp + CC));
        float2 v2 = __half22float2(*(const __half2*)(rowp + 2 * CC));
        Q[e][t][d] = q2.x; Q[e][t][d + 1] = q2.y;
        K[e][t][d] = k2.x; K[e][t][d + 1] = k2.y;
        V[e][t][d] = v2.x; V[e][t][d + 1] = v2.y;
    }
    __syncthreads();

    const float scale = 0.125f;
    for (int idx = threadIdx.x; idx < 2 * TT * TT; idx += 256) {
        int e = idx / (TT * TT), rem = idx - e * TT * TT;
        int tq = rem / TT, tk = rem - tq * TT;
        if (tk <= tq) {
            float s = 0.f;
#pragma unroll
            for (int d = 0; d < DD; d++) s += Q[e][tq][d] * K[e][tk][d];
            S[e][tq][tk] = s * scale;
        }
    }
    __syncthreads();

    if (threadIdx.x < 2 * TT) {
        int e = threadIdx.x / TT, tq = threadIdx.x - e * TT;
        float mx = -1e30f;
        for (int tk = 0; tk <= tq; tk++) mx = fmaxf(mx, S[e][tq][tk]);
        float sum = 0.f;
        for (int tk = 0; tk <= tq; tk++) {
            float ex = __expf(S[e][tq][tk] - mx);
            S[e][tq][tk] = ex;
            sum += ex;
        }
        float inv = 1.f / sum;
        for (int tk = 0; tk <= tq; tk++) S[e][tq][tk] *= inv;
    }
    __syncthreads();

    for (int idx = threadIdx.x; idx < 2 * TT * DD; idx += 256) {
        int e = idx >> 10;                 // / (TT*DD) = /1280 -> 0 or 1? 1280 not pow2
        e = idx / (TT * DD);
        int rem = idx - e * TT * DD;
        int t = rem >> 6, d = rem & 63;
        float o = 0.f;
        for (int tk = 0; tk <= t; tk++) o += S[e][t][tk] * V[e][tk][d];
        y[((size_t)b * TT + t) * CC + (hp * 2 + e) * DD + d] = __float2half(o);
    }
}

// ---------------------------------------------------------------------------
// Predictor: xn (fp16) . pred_w (fp32), V=2. One warp per token.
// ---------------------------------------------------------------------------
__global__ void pred_kernel(const __half* __restrict__ xn,
                            const float* __restrict__ pw,
                            const float* __restrict__ pb,
                            float* __restrict__ out) {
    int m = blockIdx.x * 4 + (threadIdx.x >> 5);
    int lane = threadIdx.x & 31;
    const __half* p = xn + (size_t)m * CC;
    float a0 = 0.f, a1 = 0.f;
    for (int c = lane; c < CC; c += 32) {
        float v = __half2float(p[c]);
        a0 += v * pw[c * 2 + 0];
        a1 += v * pw[c * 2 + 1];
    }
#pragma unroll
    for (int o = 16; o > 0; o >>= 1) {
        a0 += __shfl_xor_sync(0xffffffff, a0, o);
        a1 += __shfl_xor_sync(0xffffffff, a1, o);
    }
    if (lane == 0) {
        out[m * 2 + 0] = a0 + pb[0];
        out[m * 2 + 1] = a1 + pb[1];
    }
}

// ---------------------------------------------------------------------------
// Launch
// ---------------------------------------------------------------------------
extern "C" void kernel_launch(void* const* d_in, const int* in_sizes, int n_in,
                              void* d_out, int out_size) {
    const float* x      = (const float*)d_in[0];
    const float* enc_w  = (const float*)d_in[1];
    const float* enc_b  = (const float*)d_in[2];
    const float* wpe    = (const float*)d_in[3];
    const float* ln1_w  = (const float*)d_in[4];
    const float* ln1_b  = (const float*)d_in[5];
    const float* attn_w = (const float*)d_in[6];
    const float* attn_b = (const float*)d_in[7];
    const float* proj_w = (const float*)d_in[8];
    const float* proj_b = (const float*)d_in[9];
    const float* ln2_w  = (const float*)d_in[10];
    const float* ln2_b  = (const float*)d_in[11];
    const float* fc1_w  = (const float*)d_in[12];
    const float* fc1_b  = (const float*)d_in[13];
    const float* fc2_w  = (const float*)d_in[14];
    const float* fc2_b  = (const float*)d_in[15];
    const float* lnf_w  = (const float*)d_in[16];
    const float* lnf_b  = (const float*)d_in[17];
    const float* pred_w = (const float*)d_in[18];
    const float* pred_b = (const float*)d_in[19];

    float* h;
    __half *xn, *qkv, *y, *mid, *wt;
    cudaGetSymbolAddress((void**)&h,   g_h);
    cudaGetSymbolAddress((void**)&xn,  g_xn);
    cudaGetSymbolAddress((void**)&qkv, g_qkv);
    cudaGetSymbolAddress((void**)&y,   g_y);
    cudaGetSymbolAddress((void**)&mid, g_mid);
    cudaGetSymbolAddress((void**)&wt,  g_wt);

    cudaFuncSetAttribute(hgemm_kernel<0>, cudaFuncAttributeMaxDynamicSharedMemorySize, HG_SMEM);
    cudaFuncSetAttribute(hgemm_kernel<1>, cudaFuncAttributeMaxDynamicSharedMemorySize, HG_SMEM);
    cudaFuncSetAttribute(hgemm_kernel<2>, cudaFuncAttributeMaxDynamicSharedMemorySize, HG_SMEM);

    // launch 0: weight transpose + fp16 convert
    wtrans_kernel<<<dim3(64, 64, 32), dim3(32, 8)>>>(attn_w, proj_w, fc1_w, fc2_w, wt);
    // launch 1
    encode_kernel<<<(MTOK * CC + 255) / 256, 256>>>(x, enc_w, enc_b, wpe, h);

    dim3 gQKV(3 * CC / 128, MTOK / 128);   // 12 x 160
    dim3 gC  (CC / 128,     MTOK / 128);   //  4 x 160
    dim3 gFC1(4 * CC / 128, MTOK / 128);   // 16 x 160

    for (int l = 0; l < LL; l++) {
        ln_kernel<<<MTOK, 128>>>(h, ln1_w + l * CC, ln1_b + l * CC, xn);
        hgemm_kernel<0><<<gQKV, 256, HG_SMEM>>>(xn, wt + WATTN_OFF + (size_t)l * CC * 3 * CC,
                                                attn_b + (size_t)l * 3 * CC, nullptr,
                                                (void*)qkv, 3 * CC, CC);
        attn_kernel<<<BB * 4, 256>>>(qkv, y);
        hgemm_kernel<2><<<gC, 256, HG_SMEM>>>(y, wt + WPROJ_OFF + (size_t)l * CC * CC,
                                              proj_b + (size_t)l * CC, h,
                                              (void*)h, CC, CC);
        ln_kernel<<<MTOK, 128>>>(h, ln2_w + l * CC, ln2_b + l * CC, xn);
        hgemm_kernel<1><<<gFC1, 256, HG_SMEM>>>(xn, wt + WFC1_OFF + (size_t)l * CC * 4 * CC,
                                                fc1_b + (size_t)l * 4 * CC, nullptr,
                                                (void*)mid, 4 * CC, CC);
        hgemm_kernel<2><<<gC, 256, HG_SMEM>>>(mid, wt + WFC2_OFF + (size_t)l * 4 * CC * CC,
                                              fc2_b + (size_t)l * CC, h,
                                              (void*)h, CC, 4 * CC);
    }

    ln_kernel<<<MTOK, 128>>>(h, lnf_w, lnf_b, xn);
    pred_kernel<<<MTOK / 4, 128>>>(xn, pred_w, pred_b, (float*)d_out);
}